// round 4
// baseline (speedup 1.0000x reference)
#include <cuda_runtime.h>
#include <cuda_fp16.h>
#include <cstdint>

// ---------------- problem dims ----------------
#define M_DIM 4096
#define N_DIM 1024
#define E_DIM 16
#define I_DIM 1024
#define K_DIM 16384

// ---------------- GEMM config -----------------
#define BM 128
#define BN 128
#define BK 64
#define STAGES 3
#define NTHREADS 128      // 4 warps, 2x2 warp grid, 64x64 warp tile

// per-stage smem (bytes): A[128][64] fp16 (16KB) + B[64][128] fp16 (16KB)
#define A_OFF 0
#define B_OFF 16384
#define STAGE_BYTES 32768

// ---------------- device scratch --------------
__device__ __align__(1024) __half g_A[(size_t)M_DIM * K_DIM];   // 128 MiB: cw*x in fp16
__device__ __align__(1024) __half g_W[(size_t)K_DIM * N_DIM];   // 32 MiB:  W in fp16 [k][o]
__device__ __align__(1024) float  g_C0[(size_t)M_DIM * N_DIM];  // 16 MiB:  cw @ bias

// ---------------- prep kernels ----------------
__global__ void prep_w_kernel(const float* __restrict__ W) {
    size_t idx    = (size_t)blockIdx.x * blockDim.x + threadIdx.x;
    size_t stride = (size_t)gridDim.x * blockDim.x;
    const size_t total4 = (size_t)K_DIM * N_DIM / 4;
    for (; idx < total4; idx += stride) {
        float4 w = *reinterpret_cast<const float4*>(W + idx * 4);
        __half2 h01 = __floats2half2_rn(w.x, w.y);
        __half2 h23 = __floats2half2_rn(w.z, w.w);
        *reinterpret_cast<__half2*>(g_W + idx * 4)     = h01;
        *reinterpret_cast<__half2*>(g_W + idx * 4 + 2) = h23;
    }
}

__global__ void prep_a_kernel(const float* __restrict__ x,
                              const float* __restrict__ cw) {
    size_t idx    = (size_t)blockIdx.x * blockDim.x + threadIdx.x;
    size_t stride = (size_t)gridDim.x * blockDim.x;
    const size_t total4 = (size_t)M_DIM * K_DIM / 4;
    for (; idx < total4; idx += stride) {
        size_t base = idx * 4;
        size_t b = base >> 14;
        int    k = (int)(base & 16383);
        int    e = k >> 10;
        int    i = k & 1023;
        float c = cw[b * E_DIM + e];
        float4 xv = *reinterpret_cast<const float4*>(x + (b << 10) + i);
        __half2 h01 = __floats2half2_rn(c * xv.x, c * xv.y);
        __half2 h23 = __floats2half2_rn(c * xv.z, c * xv.w);
        *reinterpret_cast<__half2*>(g_A + base)     = h01;
        *reinterpret_cast<__half2*>(g_A + base + 2) = h23;
    }
}

__global__ void prep_c0_kernel(const float* __restrict__ cw,
                               const float* __restrict__ bias) {
    size_t idx = (size_t)blockIdx.x * blockDim.x + threadIdx.x;
    if (idx >= (size_t)M_DIM * N_DIM) return;
    size_t b = idx >> 10;
    int    o = (int)(idx & 1023);
    float s = 0.f;
#pragma unroll
    for (int n = 0; n < E_DIM; ++n)
        s += cw[b * E_DIM + n] * bias[n * N_DIM + o];
    g_C0[idx] = s;
}

// ---------------- asm helpers ----------------
__device__ __forceinline__ void cp_async16(uint32_t s, const void* g) {
    asm volatile("cp.async.cg.shared.global [%0], [%1], 16;\n" :: "r"(s), "l"(g));
}
__device__ __forceinline__ void cp_commit() {
    asm volatile("cp.async.commit_group;\n" ::: "memory");
}
template <int N>
__device__ __forceinline__ void cp_wait() {
    asm volatile("cp.async.wait_group %0;\n" :: "n"(N) : "memory");
}
__device__ __forceinline__ void ldsm_x4(uint32_t* r, uint32_t addr) {
    asm volatile("ldmatrix.sync.aligned.m8n8.x4.shared.b16 {%0,%1,%2,%3}, [%4];"
                 : "=r"(r[0]), "=r"(r[1]), "=r"(r[2]), "=r"(r[3]) : "r"(addr));
}
__device__ __forceinline__ void ldsm_x4_t(uint32_t* r, uint32_t addr) {
    asm volatile("ldmatrix.sync.aligned.m8n8.x4.trans.shared.b16 {%0,%1,%2,%3}, [%4];"
                 : "=r"(r[0]), "=r"(r[1]), "=r"(r[2]), "=r"(r[3]) : "r"(addr));
}
__device__ __forceinline__ void mma_f16(float* c, const uint32_t* a, const uint32_t* b) {
    asm volatile(
        "mma.sync.aligned.m16n8k16.row.col.f32.f16.f16.f32 "
        "{%0,%1,%2,%3}, {%4,%5,%6,%7}, {%8,%9}, {%0,%1,%2,%3};"
        : "+f"(c[0]), "+f"(c[1]), "+f"(c[2]), "+f"(c[3])
        : "r"(a[0]), "r"(a[1]), "r"(a[2]), "r"(a[3]), "r"(b[0]), "r"(b[1]));
}

// ---------------- tile loader ----------------
// A tile: [128 rows][64 k] fp16, row = 128B = 8 x 16B chunks, swizzle: ch ^ (row & 7)
//   thread t -> row t, chunks 0..7 (128B contiguous per thread)
// B tile: [64 k-rows][128 n] fp16, row = 256B = 16 chunks, swizzle: ch ^ (r & 7)
//   thread t -> row t>>1, chunks (t&1)*8 .. +7 (128B contiguous per thread)
__device__ __forceinline__ void issue_stage(uint32_t st,
                                            const __half* pA, const __half* pB,
                                            const uint32_t* dstA,
                                            const uint32_t* dstB) {
#pragma unroll
    for (int p = 0; p < 8; ++p)
        cp_async16(st + A_OFF + dstA[p], pA + p * 8);
#pragma unroll
    for (int p = 0; p < 8; ++p)
        cp_async16(st + B_OFF + dstB[p], pB + (size_t)p * 8);
}

// ---------------- main GEMM (fp16 HMMA, 64x64 warp tiles) --------------------
__global__ void __launch_bounds__(NTHREADS, 2)
gemm_kernel(float* __restrict__ out) {
    extern __shared__ char smem_raw[];
    const uint32_t smem_base = (uint32_t)__cvta_generic_to_shared(smem_raw);
    const int tid  = threadIdx.x;
    const int lane = tid & 31;
    const int warp = tid >> 5;
    const int wm   = warp >> 1;   // 0..1
    const int wn   = warp & 1;    // 0..1
    const int bm0  = blockIdx.y * BM;
    const int bn0  = blockIdx.x * BN;

    // producer: A row = tid (8 chunks), B row = tid>>1, chunk base (tid&1)*8
    const int arow = tid;
    const int brow = tid >> 1, bc0 = (tid & 1) * 8;
    uint32_t dstA[8], dstB[8];
#pragma unroll
    for (int p = 0; p < 8; ++p) {
        dstA[p] = (uint32_t)(arow * 128 + ((p ^ (arow & 7)) << 4));
        dstB[p] = (uint32_t)(brow * 256 + (((bc0 + p) ^ (brow & 7)) << 4));
    }
    const __half* pA = g_A + (size_t)(bm0 + arow) * K_DIM;
    const __half* pB = g_W + (size_t)brow * N_DIM + bn0 + bc0 * 8;

    float c[4][8][4];
#pragma unroll
    for (int i = 0; i < 4; ++i)
#pragma unroll
        for (int j = 0; j < 8; ++j)
#pragma unroll
            for (int k = 0; k < 4; ++k) c[i][j][k] = 0.f;

    const int KT = K_DIM / BK;  // 256

#pragma unroll
    for (int s = 0; s < STAGES - 1; ++s) {
        issue_stage(smem_base + s * STAGE_BYTES, pA, pB, dstA, dstB);
        pA += BK; pB += (size_t)BK * N_DIM;
        cp_commit();
    }

    const int a_row16 = lane & 15;
    const int hi_half = lane >> 4;

    int buf = 0;
    for (int kt = 0; kt < KT; ++kt) {
        cp_wait<STAGES - 2>();
        __syncthreads();

        int load_buf = buf + (STAGES - 1);
        if (load_buf >= STAGES) load_buf -= STAGES;
        if (kt + STAGES - 1 < KT) {
            issue_stage(smem_base + load_buf * STAGE_BYTES, pA, pB, dstA, dstB);
            pA += BK; pB += (size_t)BK * N_DIM;
        }
        cp_commit();

        const uint32_t st = smem_base + buf * STAGE_BYTES;
#pragma unroll
        for (int s = 0; s < 4; ++s) {       // four k16 steps per BK=64
            uint32_t a[4][4];
#pragma unroll
            for (int mt = 0; mt < 4; ++mt) {
                int row = wm * 64 + mt * 16 + a_row16;
                int ch  = s * 2 + hi_half;
                uint32_t off = (uint32_t)(row * 128 + ((ch ^ (row & 7)) << 4));
                ldsm_x4(a[mt], st + A_OFF + off);
            }
            uint32_t b[8][2];
#pragma unroll
            for (int ntp = 0; ntp < 4; ++ntp) {
                int r  = s * 16 + (lane & 15);
                int ch = wn * 8 + ntp * 2 + hi_half;
                uint32_t off = (uint32_t)(r * 256 + ((ch ^ (r & 7)) << 4));
                uint32_t t[4];
                ldsm_x4_t(t, st + B_OFF + off);
                b[ntp * 2][0] = t[0];     b[ntp * 2][1] = t[1];
                b[ntp * 2 + 1][0] = t[2]; b[ntp * 2 + 1][1] = t[3];
            }
#pragma unroll
            for (int mt = 0; mt < 4; ++mt)
#pragma unroll
                for (int nt = 0; nt < 8; ++nt)
                    mma_f16(c[mt][nt], a[mt], b[nt]);
        }
        buf = (buf + 1 == STAGES) ? 0 : buf + 1;
    }

    // epilogue: add cw@bias term, ReLU, store fp32
    const int gr = lane >> 2;
    const int ct = lane & 3;
#pragma unroll
    for (int mt = 0; mt < 4; ++mt) {
#pragma unroll
        for (int nt = 0; nt < 8; ++nt) {
            int row = bm0 + wm * 64 + mt * 16 + gr;
            int o   = bn0 + wn * 64 + nt * 8 + ct * 2;
            size_t i0 = (size_t)row * N_DIM + o;
            out[i0]     = fmaxf(c[mt][nt][0] + g_C0[i0], 0.f);
            out[i0 + 1] = fmaxf(c[mt][nt][1] + g_C0[i0 + 1], 0.f);
            size_t i1 = i0 + (size_t)8 * N_DIM;
            out[i1]     = fmaxf(c[mt][nt][2] + g_C0[i1], 0.f);
            out[i1 + 1] = fmaxf(c[mt][nt][3] + g_C0[i1 + 1], 0.f);
        }
    }
}

// ---------------- launch -----------------------------------------------------
extern "C" void kernel_launch(void* const* d_in, const int* in_sizes, int n_in,
                              void* d_out, int out_size) {
    const float* x = nullptr;
    const float* cw = nullptr;
    const float* W = nullptr;
    const float* bias = nullptr;
    for (int i = 0; i < n_in; ++i) {
        switch (in_sizes[i]) {
            case M_DIM * I_DIM:         x    = (const float*)d_in[i]; break;
            case M_DIM * E_DIM:         cw   = (const float*)d_in[i]; break;
            case E_DIM * I_DIM * N_DIM: W    = (const float*)d_in[i]; break;
            case E_DIM * N_DIM:         bias = (const float*)d_in[i]; break;
            default: break;
        }
    }
    float* out = (float*)d_out;

    prep_w_kernel<<<2048, 256>>>(W);
    prep_a_kernel<<<8192, 256>>>(x, cw);
    prep_c0_kernel<<<(M_DIM * N_DIM + 255) / 256, 256>>>(cw, bias);

    cudaFuncSetAttribute(gemm_kernel, cudaFuncAttributeMaxDynamicSharedMemorySize,
                         STAGES * STAGE_BYTES);
    dim3 grid(N_DIM / BN, M_DIM / BM);  // (8, 32) = 256 CTAs
    gemm_kernel<<<grid, NTHREADS, STAGES * STAGE_BYTES>>>(out);
}

// round 5
// speedup vs baseline: 1.1623x; 1.1623x over previous
#include <cuda_runtime.h>
#include <cuda_fp16.h>
#include <cstdint>

// ---------------- problem dims ----------------
#define M_DIM 4096
#define N_DIM 1024
#define E_DIM 16
#define I_DIM 1024
#define K_DIM 16384

// ---------------- GEMM config -----------------
#define BM 128
#define BN 128
#define BK 64
#define STAGES 3
#define NTHREADS 256   // 8 warps, 2x4 grid, 64x32 warp tiles

// per-stage smem: A[128 m][64 k] fp16 (16KB) + B[128 n][64 k] fp16 (16KB)
#define A_OFF 0
#define B_OFF 16384
#define STAGE_BYTES 32768

// ---------------- device scratch --------------
__device__ __align__(1024) __half g_A [(size_t)M_DIM * K_DIM];  // 128 MiB: cw*x fp16
__device__ __align__(1024) __half g_Wt[(size_t)N_DIM * K_DIM];  // 32 MiB:  W^T fp16 [n][k]
__device__ __align__(1024) float  g_C0[(size_t)M_DIM * N_DIM];  // 16 MiB:  cw @ bias

// ---------------- prep kernels ----------------
// Transpose W[k][o] -> Wt[o][k] fp16
__global__ void prep_w_kernel(const float* __restrict__ W) {
    __shared__ float t[32][33];
    const int k0 = blockIdx.x * 32, o0 = blockIdx.y * 32;
    const int tx = threadIdx.x, ty = threadIdx.y;  // 32 x 8
#pragma unroll
    for (int i = 0; i < 4; ++i)
        t[ty + i * 8][tx] = W[(size_t)(k0 + ty + i * 8) * N_DIM + o0 + tx];
    __syncthreads();
#pragma unroll
    for (int i = 0; i < 4; ++i) {
        float v = t[tx][ty + i * 8];
        g_Wt[(size_t)(o0 + ty + i * 8) * K_DIM + k0 + tx] = __float2half_rn(v);
    }
}

__global__ void prep_a_kernel(const float* __restrict__ x,
                              const float* __restrict__ cw) {
    size_t idx    = (size_t)blockIdx.x * blockDim.x + threadIdx.x;
    size_t stride = (size_t)gridDim.x * blockDim.x;
    const size_t total4 = (size_t)M_DIM * K_DIM / 4;
    for (; idx < total4; idx += stride) {
        size_t base = idx * 4;
        size_t b = base >> 14;
        int    k = (int)(base & 16383);
        int    e = k >> 10;
        int    i = k & 1023;
        float c = cw[b * E_DIM + e];
        float4 xv = *reinterpret_cast<const float4*>(x + (b << 10) + i);
        __half2 h01 = __floats2half2_rn(c * xv.x, c * xv.y);
        __half2 h23 = __floats2half2_rn(c * xv.z, c * xv.w);
        *reinterpret_cast<__half2*>(g_A + base)     = h01;
        *reinterpret_cast<__half2*>(g_A + base + 2) = h23;
    }
}

__global__ void prep_c0_kernel(const float* __restrict__ cw,
                               const float* __restrict__ bias) {
    size_t idx = (size_t)blockIdx.x * blockDim.x + threadIdx.x;
    if (idx >= (size_t)M_DIM * N_DIM) return;
    size_t b = idx >> 10;
    int    o = (int)(idx & 1023);
    float s = 0.f;
#pragma unroll
    for (int n = 0; n < E_DIM; ++n)
        s += cw[b * E_DIM + n] * bias[n * N_DIM + o];
    g_C0[idx] = s;
}

// ---------------- asm helpers ----------------
__device__ __forceinline__ void cp_async16(uint32_t s, const void* g) {
    asm volatile("cp.async.cg.shared.global [%0], [%1], 16;\n" :: "r"(s), "l"(g));
}
__device__ __forceinline__ void cp_commit() {
    asm volatile("cp.async.commit_group;\n" ::: "memory");
}
template <int N>
__device__ __forceinline__ void cp_wait() {
    asm volatile("cp.async.wait_group %0;\n" :: "n"(N) : "memory");
}
__device__ __forceinline__ void ldsm_x4(uint32_t* r, uint32_t addr) {
    asm volatile("ldmatrix.sync.aligned.m8n8.x4.shared.b16 {%0,%1,%2,%3}, [%4];"
                 : "=r"(r[0]), "=r"(r[1]), "=r"(r[2]), "=r"(r[3]) : "r"(addr));
}
__device__ __forceinline__ void mma_f16(float* c, const uint32_t* a, const uint32_t* b) {
    asm volatile(
        "mma.sync.aligned.m16n8k16.row.col.f32.f16.f16.f32 "
        "{%0,%1,%2,%3}, {%4,%5,%6,%7}, {%8,%9}, {%0,%1,%2,%3};"
        : "+f"(c[0]), "+f"(c[1]), "+f"(c[2]), "+f"(c[3])
        : "r"(a[0]), "r"(a[1]), "r"(a[2]), "r"(a[3]), "r"(b[0]), "r"(b[1]));
}

// ---------------- fragment loads ----------------
// Both tiles: [128 rows][64 k] fp16, row = 128B = 8 chunks, swizzle ch ^ (row & 7)
__device__ __forceinline__ void load_frags(uint32_t st, int s,
                                           int wm, int wn, int lane,
                                           uint32_t a[4][4], uint32_t b[4][2]) {
    const int r16 = lane & 15;
    const int hh  = lane >> 4;
#pragma unroll
    for (int mt = 0; mt < 4; ++mt) {
        int row = wm * 64 + mt * 16 + r16;
        int ch  = s * 2 + hh;
        ldsm_x4(a[mt], st + A_OFF + (uint32_t)(row * 128 + ((ch ^ (row & 7)) << 4)));
    }
    // B: one ldsm_x4 covers 16 n x 16 k (2 nt fragments), non-trans on W^T rows
    const int m  = lane >> 3;           // matrix id 0..3
    const int rr = lane & 7;
#pragma unroll
    for (int ntp = 0; ntp < 2; ++ntp) {
        int n  = wn * 32 + ntp * 16 + ((m >> 1) << 3) + rr;
        int ch = s * 2 + (m & 1);
        uint32_t t[4];
        ldsm_x4(t, st + B_OFF + (uint32_t)(n * 128 + ((ch ^ (n & 7)) << 4)));
        b[ntp * 2][0] = t[0];     b[ntp * 2][1] = t[1];
        b[ntp * 2 + 1][0] = t[2]; b[ntp * 2 + 1][1] = t[3];
    }
}

// ---------------- main GEMM -------------------
__global__ void __launch_bounds__(NTHREADS, 2)
gemm_kernel(float* __restrict__ out) {
    extern __shared__ char smem_raw[];
    const uint32_t smem_base = (uint32_t)__cvta_generic_to_shared(smem_raw);
    const int tid  = threadIdx.x;
    const int lane = tid & 31;
    const int warp = tid >> 5;
    const int wm   = warp >> 2;   // 0..1
    const int wn   = warp & 3;    // 0..3
    const int bm0  = blockIdx.y * BM;
    const int bn0  = blockIdx.x * BN;

    // producer: thread t loads row t of A tile and row t of B tile (8 chunks each)
    const int prow = tid >> 1;               // 0..127 (two threads per row)
    const int pch0 = (tid & 1) * 4;          // chunks 0-3 or 4-7
    const uint32_t psw = (uint32_t)(prow * 128);
    const int pxor = prow & 7;
    const __half* pA = g_A  + (size_t)(bm0 + prow) * K_DIM + pch0 * 8;
    const __half* pB = g_Wt + (size_t)(bn0 + prow) * K_DIM + pch0 * 8;

    float c[4][4][4];
#pragma unroll
    for (int i = 0; i < 4; ++i)
#pragma unroll
        for (int j = 0; j < 4; ++j)
#pragma unroll
            for (int k = 0; k < 4; ++k) c[i][j][k] = 0.f;

    const int KT = K_DIM / BK;  // 256

#pragma unroll
    for (int s = 0; s < STAGES - 1; ++s) {
        const uint32_t st = smem_base + s * STAGE_BYTES;
#pragma unroll
        for (int p = 0; p < 4; ++p) {
            uint32_t so = psw + ((uint32_t)((pch0 + p) ^ pxor) << 4);
            cp_async16(st + A_OFF + so, pA + p * 8);
            cp_async16(st + B_OFF + so, pB + p * 8);
        }
        pA += BK; pB += BK;
        cp_commit();
    }

    uint32_t af[2][4][4], bf[2][4][2];

    int buf = 0;
    for (int kt = 0; kt < KT; ++kt) {
        cp_wait<STAGES - 2>();
        __syncthreads();

        int load_buf = buf + (STAGES - 1);
        if (load_buf >= STAGES) load_buf -= STAGES;
        if (kt + STAGES - 1 < KT) {
            const uint32_t st = smem_base + load_buf * STAGE_BYTES;
#pragma unroll
            for (int p = 0; p < 4; ++p) {
                uint32_t so = psw + ((uint32_t)((pch0 + p) ^ pxor) << 4);
                cp_async16(st + A_OFF + so, pA + p * 8);
                cp_async16(st + B_OFF + so, pB + p * 8);
            }
            pA += BK; pB += BK;
        }
        cp_commit();

        const uint32_t st = smem_base + buf * STAGE_BYTES;
        load_frags(st, 0, wm, wn, lane, af[0], bf[0]);
#pragma unroll
        for (int s = 0; s < 4; ++s) {
            if (s < 3)
                load_frags(st, s + 1, wm, wn, lane, af[(s + 1) & 1], bf[(s + 1) & 1]);
            const int cur = s & 1;
#pragma unroll
            for (int mt = 0; mt < 4; ++mt)
#pragma unroll
                for (int nt = 0; nt < 4; ++nt)
                    mma_f16(c[mt][nt], af[cur][mt], bf[cur][nt]);
        }
        buf = (buf + 1 == STAGES) ? 0 : buf + 1;
    }

    // epilogue: add cw@bias term, ReLU, store fp32
    const int gr = lane >> 2;
    const int ct = lane & 3;
#pragma unroll
    for (int mt = 0; mt < 4; ++mt) {
#pragma unroll
        for (int nt = 0; nt < 4; ++nt) {
            int row = bm0 + wm * 64 + mt * 16 + gr;
            int o   = bn0 + wn * 32 + nt * 8 + ct * 2;
            size_t i0 = (size_t)row * N_DIM + o;
            out[i0]     = fmaxf(c[mt][nt][0] + g_C0[i0], 0.f);
            out[i0 + 1] = fmaxf(c[mt][nt][1] + g_C0[i0 + 1], 0.f);
            size_t i1 = i0 + (size_t)8 * N_DIM;
            out[i1]     = fmaxf(c[mt][nt][2] + g_C0[i1], 0.f);
            out[i1 + 1] = fmaxf(c[mt][nt][3] + g_C0[i1 + 1], 0.f);
        }
    }
}

// ---------------- launch -----------------------------------------------------
extern "C" void kernel_launch(void* const* d_in, const int* in_sizes, int n_in,
                              void* d_out, int out_size) {
    const float* x = nullptr;
    const float* cw = nullptr;
    const float* W = nullptr;
    const float* bias = nullptr;
    for (int i = 0; i < n_in; ++i) {
        switch (in_sizes[i]) {
            case M_DIM * I_DIM:         x    = (const float*)d_in[i]; break;
            case M_DIM * E_DIM:         cw   = (const float*)d_in[i]; break;
            case E_DIM * I_DIM * N_DIM: W    = (const float*)d_in[i]; break;
            case E_DIM * N_DIM:         bias = (const float*)d_in[i]; break;
            default: break;
        }
    }
    float* out = (float*)d_out;

    prep_w_kernel<<<dim3(K_DIM / 32, N_DIM / 32), dim3(32, 8)>>>(W);
    prep_a_kernel<<<8192, 256>>>(x, cw);
    prep_c0_kernel<<<(M_DIM * N_DIM + 255) / 256, 256>>>(cw, bias);

    cudaFuncSetAttribute(gemm_kernel, cudaFuncAttributeMaxDynamicSharedMemorySize,
                         STAGES * STAGE_BYTES);
    dim3 grid(N_DIM / BN, M_DIM / BM);  // (8, 32) = 256 CTAs
    gemm_kernel<<<grid, NTHREADS, STAGES * STAGE_BYTES>>>(out);
}

// round 6
// speedup vs baseline: 1.2750x; 1.0969x over previous
#include <cuda_runtime.h>
#include <cuda_fp16.h>
#include <cstdint>

// ---------------- problem dims ----------------
#define M_DIM 4096
#define N_DIM 1024
#define E_DIM 16
#define I_DIM 1024
#define K_DIM 16384

// ---------------- GEMM config -----------------
#define BM 128
#define BN 128
#define BK 64
#define STAGES 6
#define NTHREADS 512   // 16 warps, 4x4 grid, 32x32 warp tiles

// per-stage smem: A[128 m][64 k] fp16 (16KB) + B(W^T)[128 n][64 k] fp16 (16KB)
#define A_OFF 0
#define B_OFF 16384
#define STAGE_BYTES 32768
#define SMEM_TOTAL (STAGES * STAGE_BYTES)   // 196608

// ---------------- device scratch --------------
__device__ __align__(1024) __half g_A [(size_t)M_DIM * K_DIM];  // 128 MiB: cw*x fp16
__device__ __align__(1024) __half g_Wt[(size_t)N_DIM * K_DIM];  // 32 MiB:  W^T fp16 [n][k]
__device__ __align__(1024) float  g_C0[(size_t)M_DIM * N_DIM];  // 16 MiB:  cw @ bias

// ---------------- prep kernels ----------------
__global__ void prep_w_kernel(const float* __restrict__ W) {
    __shared__ float t[32][33];
    const int k0 = blockIdx.x * 32, o0 = blockIdx.y * 32;
    const int tx = threadIdx.x, ty = threadIdx.y;  // 32 x 8
#pragma unroll
    for (int i = 0; i < 4; ++i)
        t[ty + i * 8][tx] = W[(size_t)(k0 + ty + i * 8) * N_DIM + o0 + tx];
    __syncthreads();
#pragma unroll
    for (int i = 0; i < 4; ++i) {
        float v = t[tx][ty + i * 8];
        g_Wt[(size_t)(o0 + ty + i * 8) * K_DIM + k0 + tx] = __float2half_rn(v);
    }
}

__global__ void prep_a_kernel(const float* __restrict__ x,
                              const float* __restrict__ cw) {
    size_t idx    = (size_t)blockIdx.x * blockDim.x + threadIdx.x;
    size_t stride = (size_t)gridDim.x * blockDim.x;
    const size_t total4 = (size_t)M_DIM * K_DIM / 4;
    for (; idx < total4; idx += stride) {
        size_t base = idx * 4;
        size_t b = base >> 14;
        int    k = (int)(base & 16383);
        int    e = k >> 10;
        int    i = k & 1023;
        float c = cw[b * E_DIM + e];
        float4 xv = *reinterpret_cast<const float4*>(x + (b << 10) + i);
        __half2 h01 = __floats2half2_rn(c * xv.x, c * xv.y);
        __half2 h23 = __floats2half2_rn(c * xv.z, c * xv.w);
        *reinterpret_cast<__half2*>(g_A + base)     = h01;
        *reinterpret_cast<__half2*>(g_A + base + 2) = h23;
    }
}

__global__ void prep_c0_kernel(const float* __restrict__ cw,
                               const float* __restrict__ bias) {
    size_t idx = (size_t)blockIdx.x * blockDim.x + threadIdx.x;
    if (idx >= (size_t)M_DIM * N_DIM) return;
    size_t b = idx >> 10;
    int    o = (int)(idx & 1023);
    float s = 0.f;
#pragma unroll
    for (int n = 0; n < E_DIM; ++n)
        s += cw[b * E_DIM + n] * bias[n * N_DIM + o];
    g_C0[idx] = s;
}

// ---------------- asm helpers ----------------
__device__ __forceinline__ void cp_async16(uint32_t s, const void* g) {
    asm volatile("cp.async.cg.shared.global [%0], [%1], 16;\n" :: "r"(s), "l"(g));
}
__device__ __forceinline__ void cp_commit() {
    asm volatile("cp.async.commit_group;\n" ::: "memory");
}
template <int N>
__device__ __forceinline__ void cp_wait() {
    asm volatile("cp.async.wait_group %0;\n" :: "n"(N) : "memory");
}
__device__ __forceinline__ void ldsm_x4(uint32_t* r, uint32_t addr) {
    asm volatile("ldmatrix.sync.aligned.m8n8.x4.shared.b16 {%0,%1,%2,%3}, [%4];"
                 : "=r"(r[0]), "=r"(r[1]), "=r"(r[2]), "=r"(r[3]) : "r"(addr));
}
__device__ __forceinline__ void mma_f16(float* c, const uint32_t* a, const uint32_t* b) {
    asm volatile(
        "mma.sync.aligned.m16n8k16.row.col.f32.f16.f16.f32 "
        "{%0,%1,%2,%3}, {%4,%5,%6,%7}, {%8,%9}, {%0,%1,%2,%3};"
        : "+f"(c[0]), "+f"(c[1]), "+f"(c[2]), "+f"(c[3])
        : "r"(a[0]), "r"(a[1]), "r"(a[2]), "r"(a[3]), "r"(b[0]), "r"(b[1]));
}

// ---------------- main GEMM -------------------
// Both smem tiles [128 rows][64 k] fp16, row = 128B = 8 chunks, swizzle ch ^ (row & 7)
__global__ void __launch_bounds__(NTHREADS, 1)
gemm_kernel(float* __restrict__ out) {
    extern __shared__ char smem_raw[];
    const uint32_t smem_base = (uint32_t)__cvta_generic_to_shared(smem_raw);
    const int tid  = threadIdx.x;
    const int lane = tid & 31;
    const int warp = tid >> 5;
    const int wm   = warp >> 2;   // 0..3
    const int wn   = warp & 3;    // 0..3
    const int bm0  = blockIdx.y * BM;
    const int bn0  = blockIdx.x * BN;

    // producer: thread t -> row t>>2 (0..127), chunk pair (t&3)*2
    const int prow = tid >> 2;
    const int pc0  = (tid & 3) * 2;
    const uint32_t psw = (uint32_t)(prow * 128);
    const int pxor = prow & 7;
    const __half* pA = g_A  + (size_t)(bm0 + prow) * K_DIM + pc0 * 8;
    const __half* pB = g_Wt + (size_t)(bn0 + prow) * K_DIM + pc0 * 8;

    float c[2][4][4];
#pragma unroll
    for (int i = 0; i < 2; ++i)
#pragma unroll
        for (int j = 0; j < 4; ++j)
#pragma unroll
            for (int k = 0; k < 4; ++k) c[i][j][k] = 0.f;

    const int KT = K_DIM / BK;  // 256

#pragma unroll
    for (int s = 0; s < STAGES - 1; ++s) {
        const uint32_t st = smem_base + s * STAGE_BYTES;
#pragma unroll
        for (int p = 0; p < 2; ++p) {
            uint32_t so = psw + ((uint32_t)((pc0 + p) ^ pxor) << 4);
            cp_async16(st + A_OFF + so, pA + p * 8);
            cp_async16(st + B_OFF + so, pB + p * 8);
        }
        pA += BK; pB += BK;
        cp_commit();
    }

    const int a_r16 = lane & 15;
    const int a_hh  = lane >> 4;
    const int b_m   = lane >> 3;   // matrix id 0..3
    const int b_rr  = lane & 7;

    int buf = 0;
    for (int kt = 0; kt < KT; ++kt) {
        cp_wait<STAGES - 2>();
        __syncthreads();

        int load_buf = buf + (STAGES - 1);
        if (load_buf >= STAGES) load_buf -= STAGES;
        if (kt + STAGES - 1 < KT) {
            const uint32_t st = smem_base + load_buf * STAGE_BYTES;
#pragma unroll
            for (int p = 0; p < 2; ++p) {
                uint32_t so = psw + ((uint32_t)((pc0 + p) ^ pxor) << 4);
                cp_async16(st + A_OFF + so, pA + p * 8);
                cp_async16(st + B_OFF + so, pB + p * 8);
            }
            pA += BK; pB += BK;
        }
        cp_commit();

        const uint32_t st = smem_base + buf * STAGE_BYTES;
#pragma unroll
        for (int s = 0; s < 4; ++s) {       // four k16 steps per BK=64
            uint32_t a[2][4];
#pragma unroll
            for (int mt = 0; mt < 2; ++mt) {
                int row = wm * 32 + mt * 16 + a_r16;
                int ch  = s * 2 + a_hh;
                ldsm_x4(a[mt], st + A_OFF + (uint32_t)(row * 128 + ((ch ^ (row & 7)) << 4)));
            }
            uint32_t b[4][2];
            {
                int n  = wn * 32 + ((b_m >> 1) << 3) + b_rr;          // first 16 n
                int ch = s * 2 + (b_m & 1);
                uint32_t t[4];
                ldsm_x4(t, st + B_OFF + (uint32_t)(n * 128 + ((ch ^ (n & 7)) << 4)));
                b[0][0] = t[0]; b[0][1] = t[1];
                b[1][0] = t[2]; b[1][1] = t[3];
                int n2 = n + 16;                                       // second 16 n
                ldsm_x4(t, st + B_OFF + (uint32_t)(n2 * 128 + ((ch ^ (n2 & 7)) << 4)));
                b[2][0] = t[0]; b[2][1] = t[1];
                b[3][0] = t[2]; b[3][1] = t[3];
            }
#pragma unroll
            for (int mt = 0; mt < 2; ++mt)
#pragma unroll
                for (int nt = 0; nt < 4; ++nt)
                    mma_f16(c[mt][nt], a[mt], b[nt]);
        }
        buf = (buf + 1 == STAGES) ? 0 : buf + 1;
    }

    // epilogue: add cw@bias term, ReLU, store fp32
    const int gr = lane >> 2;
    const int ct = lane & 3;
#pragma unroll
    for (int mt = 0; mt < 2; ++mt) {
#pragma unroll
        for (int nt = 0; nt < 4; ++nt) {
            int row = bm0 + wm * 32 + mt * 16 + gr;
            int o   = bn0 + wn * 32 + nt * 8 + ct * 2;
            size_t i0 = (size_t)row * N_DIM + o;
            out[i0]     = fmaxf(c[mt][nt][0] + g_C0[i0], 0.f);
            out[i0 + 1] = fmaxf(c[mt][nt][1] + g_C0[i0 + 1], 0.f);
            size_t i1 = i0 + (size_t)8 * N_DIM;
            out[i1]     = fmaxf(c[mt][nt][2] + g_C0[i1], 0.f);
            out[i1 + 1] = fmaxf(c[mt][nt][3] + g_C0[i1 + 1], 0.f);
        }
    }
}

// ---------------- launch -----------------------------------------------------
extern "C" void kernel_launch(void* const* d_in, const int* in_sizes, int n_in,
                              void* d_out, int out_size) {
    const float* x = nullptr;
    const float* cw = nullptr;
    const float* W = nullptr;
    const float* bias = nullptr;
    for (int i = 0; i < n_in; ++i) {
        switch (in_sizes[i]) {
            case M_DIM * I_DIM:         x    = (const float*)d_in[i]; break;
            case M_DIM * E_DIM:         cw   = (const float*)d_in[i]; break;
            case E_DIM * I_DIM * N_DIM: W    = (const float*)d_in[i]; break;
            case E_DIM * N_DIM:         bias = (const float*)d_in[i]; break;
            default: break;
        }
    }
    float* out = (float*)d_out;

    prep_w_kernel<<<dim3(K_DIM / 32, N_DIM / 32), dim3(32, 8)>>>(W);
    prep_a_kernel<<<8192, 256>>>(x, cw);
    prep_c0_kernel<<<(M_DIM * N_DIM + 255) / 256, 256>>>(cw, bias);

    cudaFuncSetAttribute(gemm_kernel, cudaFuncAttributeMaxDynamicSharedMemorySize,
                         SMEM_TOTAL);
    dim3 grid(N_DIM / BN, M_DIM / BM);  // (8, 32) = 256 CTAs
    gemm_kernel<<<grid, NTHREADS, SMEM_TOTAL>>>(out);
}

// round 7
// speedup vs baseline: 1.6893x; 1.3250x over previous
#include <cuda_runtime.h>
#include <cuda_fp16.h>
#include <cstdint>

// ---------------- problem dims ----------------
#define M_DIM 4096
#define N_DIM 1024
#define E_DIM 16
#define I_DIM 1024
#define K_DIM 16384
#define KS    16448          // K extended by one BK tile carrying cw/bias rank-16 term

// ---------------- GEMM config -----------------
#define BM 128
#define BN 128
#define BK 64
#define STAGES 3
#define NTHREADS 256

// per-stage smem (bytes): A[128][64] fp16 (16KB) + B[64][128] fp16 (16KB)
#define A_OFF 0
#define B_OFF 16384
#define STAGE_BYTES 32768

// ---------------- device scratch --------------
__device__ __align__(1024) __half g_A[(size_t)M_DIM * KS];  // ~128.5 MiB: [cw*x | cw | 0]
__device__ __align__(1024) __half g_W[(size_t)KS * N_DIM];  // ~32.1 MiB:  [W ; bias ; 0] (k-major)

// ---------------- prep kernels ----------------
__global__ void prep_w_kernel(const float* __restrict__ W) {
    size_t idx    = (size_t)blockIdx.x * blockDim.x + threadIdx.x;
    size_t stride = (size_t)gridDim.x * blockDim.x;
    const size_t total4 = (size_t)K_DIM * N_DIM / 4;
    for (; idx < total4; idx += stride) {
        float4 w = *reinterpret_cast<const float4*>(W + idx * 4);
        __half2 h01 = __floats2half2_rn(w.x, w.y);
        __half2 h23 = __floats2half2_rn(w.z, w.w);
        *reinterpret_cast<__half2*>(g_W + idx * 4)     = h01;
        *reinterpret_cast<__half2*>(g_W + idx * 4 + 2) = h23;
    }
}

// A[b][k] = fp16( cw[b][k>>10] * x[b][k&1023] ), written at stride KS
__global__ void prep_a_kernel(const float* __restrict__ x,
                              const float* __restrict__ cw) {
    size_t idx    = (size_t)blockIdx.x * blockDim.x + threadIdx.x;
    size_t stride = (size_t)gridDim.x * blockDim.x;
    const size_t total4 = (size_t)M_DIM * K_DIM / 4;
    for (; idx < total4; idx += stride) {
        size_t base = idx * 4;
        size_t b = base >> 14;
        int    k = (int)(base & 16383);
        int    e = k >> 10;
        int    i = k & 1023;
        float c = cw[b * E_DIM + e];
        float4 xv = *reinterpret_cast<const float4*>(x + (b << 10) + i);
        __half2 h01 = __floats2half2_rn(c * xv.x, c * xv.y);
        __half2 h23 = __floats2half2_rn(c * xv.z, c * xv.w);
        size_t w = b * KS + k;
        *reinterpret_cast<__half2*>(g_A + w)     = h01;
        *reinterpret_cast<__half2*>(g_A + w + 2) = h23;
    }
}

// Tail K-tile: A cols 16384..16447 = [cw | 0], W rows 16384..16447 = [bias ; 0]
__global__ void prep_tail_kernel(const float* __restrict__ cw,
                                 const float* __restrict__ bias) {
    int idx = blockIdx.x * blockDim.x + threadIdx.x;
    // A side: 4096 rows x 64 cols
    if (idx < M_DIM * 64) {
        int b = idx >> 6, e = idx & 63;
        g_A[(size_t)b * KS + K_DIM + e] =
            (e < E_DIM) ? __float2half_rn(cw[b * E_DIM + e]) : __half(0.f);
    } else {
        int j = idx - M_DIM * 64;          // W side: 64 rows x 1024 cols
        if (j < 64 * N_DIM) {
            int e = j >> 10, o = j & 1023;
            g_W[(size_t)(K_DIM + e) * N_DIM + o] =
                (e < E_DIM) ? __float2half_rn(bias[e * N_DIM + o]) : __half(0.f);
        }
    }
}

// ---------------- asm helpers ----------------
__device__ __forceinline__ void cp_async16(uint32_t s, const void* g) {
    asm volatile("cp.async.cg.shared.global [%0], [%1], 16;\n" :: "r"(s), "l"(g));
}
__device__ __forceinline__ void cp_commit() {
    asm volatile("cp.async.commit_group;\n" ::: "memory");
}
template <int N>
__device__ __forceinline__ void cp_wait() {
    asm volatile("cp.async.wait_group %0;\n" :: "n"(N) : "memory");
}
__device__ __forceinline__ void ldsm_x4(uint32_t* r, uint32_t addr) {
    asm volatile("ldmatrix.sync.aligned.m8n8.x4.shared.b16 {%0,%1,%2,%3}, [%4];"
                 : "=r"(r[0]), "=r"(r[1]), "=r"(r[2]), "=r"(r[3]) : "r"(addr));
}
__device__ __forceinline__ void ldsm_x4_t(uint32_t* r, uint32_t addr) {
    asm volatile("ldmatrix.sync.aligned.m8n8.x4.trans.shared.b16 {%0,%1,%2,%3}, [%4];"
                 : "=r"(r[0]), "=r"(r[1]), "=r"(r[2]), "=r"(r[3]) : "r"(addr));
}
__device__ __forceinline__ void mma_f16(float* c, const uint32_t* a, const uint32_t* b) {
    asm volatile(
        "mma.sync.aligned.m16n8k16.row.col.f32.f16.f16.f32 "
        "{%0,%1,%2,%3}, {%4,%5,%6,%7}, {%8,%9}, {%0,%1,%2,%3};"
        : "+f"(c[0]), "+f"(c[1]), "+f"(c[2]), "+f"(c[3])
        : "r"(a[0]), "r"(a[1]), "r"(a[2]), "r"(a[3]), "r"(b[0]), "r"(b[1]));
}

// ---------------- tile loader (R3 layout) ----------------
// A tile: [128 rows][64 k] fp16, row = 128B = 8 x 16B chunks, swizzle: ch ^ (row & 7)
// B tile: [64 k-rows][128 n] fp16, row = 256B = 16 chunks,    swizzle: ch ^ (r & 7)
__device__ __forceinline__ void issue_stage(uint32_t st,
                                            const __half* pA, const __half* pB,
                                            uint32_t dstA0, uint32_t dstB0) {
#pragma unroll
    for (int p = 0; p < 4; ++p)
        cp_async16(st + A_OFF + dstA0 + p * (32 * 128),
                   pA + (size_t)p * 32 * KS);
#pragma unroll
    for (int p = 0; p < 4; ++p)
        cp_async16(st + B_OFF + dstB0 + p * (16 * 256),
                   pB + (size_t)p * 16 * N_DIM);
}

// ---------------- main GEMM (R3 core, K extended) ---------------------------
__global__ void __launch_bounds__(NTHREADS, 2)
gemm_kernel(float* __restrict__ out) {
    extern __shared__ char smem_raw[];
    const uint32_t smem_base = (uint32_t)__cvta_generic_to_shared(smem_raw);
    const int tid  = threadIdx.x;
    const int lane = tid & 31;
    const int warp = tid >> 5;
    const int wm   = warp >> 2;   // 0..1
    const int wn   = warp & 3;    // 0..3
    const int bm0  = blockIdx.y * BM;
    const int bn0  = blockIdx.x * BN;

    const int arow = tid >> 3, ach = tid & 7;
    const int brow = tid >> 4, bch = tid & 15;
    const uint32_t dstA0 = (uint32_t)(arow * 128 + ((ach ^ (arow & 7)) << 4));
    const uint32_t dstB0 = (uint32_t)(brow * 256 + ((bch ^ (brow & 7)) << 4));
    const __half* pA = g_A + (size_t)(bm0 + arow) * KS + ach * 8;
    const __half* pB = g_W + (size_t)brow * N_DIM + bn0 + bch * 8;

    float c[4][4][4];
#pragma unroll
    for (int i = 0; i < 4; ++i)
#pragma unroll
        for (int j = 0; j < 4; ++j)
#pragma unroll
            for (int k = 0; k < 4; ++k) c[i][j][k] = 0.f;

    const int KT = KS / BK;  // 257

#pragma unroll
    for (int s = 0; s < STAGES - 1; ++s) {
        issue_stage(smem_base + s * STAGE_BYTES, pA, pB, dstA0, dstB0);
        pA += BK; pB += (size_t)BK * N_DIM;
        cp_commit();
    }

    const int a_row16 = lane & 15;
    const int hi_half = lane >> 4;

    int buf = 0;
    for (int kt = 0; kt < KT; ++kt) {
        cp_wait<STAGES - 2>();
        __syncthreads();

        int load_buf = buf + (STAGES - 1);
        if (load_buf >= STAGES) load_buf -= STAGES;
        if (kt + STAGES - 1 < KT) {
            issue_stage(smem_base + load_buf * STAGE_BYTES, pA, pB, dstA0, dstB0);
            pA += BK; pB += (size_t)BK * N_DIM;
        }
        cp_commit();

        const uint32_t st = smem_base + buf * STAGE_BYTES;
#pragma unroll
        for (int s = 0; s < 4; ++s) {       // four k16 steps per BK=64
            uint32_t a[4][4];
#pragma unroll
            for (int mt = 0; mt < 4; ++mt) {
                int row = wm * 64 + mt * 16 + a_row16;
                int ch  = s * 2 + hi_half;
                uint32_t off = (uint32_t)(row * 128 + ((ch ^ (row & 7)) << 4));
                ldsm_x4(a[mt], st + A_OFF + off);
            }
            uint32_t b[4][2];
#pragma unroll
            for (int nt2 = 0; nt2 < 2; ++nt2) {
                int r  = s * 16 + (lane & 15);
                int ch = wn * 4 + nt2 * 2 + hi_half;
                uint32_t off = (uint32_t)(r * 256 + ((ch ^ (r & 7)) << 4));
                uint32_t t[4];
                ldsm_x4_t(t, st + B_OFF + off);
                b[nt2 * 2][0] = t[0];     b[nt2 * 2][1] = t[1];
                b[nt2 * 2 + 1][0] = t[2]; b[nt2 * 2 + 1][1] = t[3];
            }
#pragma unroll
            for (int mt = 0; mt < 4; ++mt)
#pragma unroll
                for (int nt = 0; nt < 4; ++nt)
                    mma_f16(c[mt][nt], a[mt], b[nt]);
        }
        buf = (buf + 1 == STAGES) ? 0 : buf + 1;
    }

    // epilogue: ReLU + store (bias term already accumulated via K-extension)
    const int gr = lane >> 2;
    const int ct = lane & 3;
#pragma unroll
    for (int mt = 0; mt < 4; ++mt) {
#pragma unroll
        for (int nt = 0; nt < 4; ++nt) {
            int row = bm0 + wm * 64 + mt * 16 + gr;
            int o   = bn0 + wn * 32 + nt * 8 + ct * 2;
            size_t i0 = (size_t)row * N_DIM + o;
            out[i0]     = fmaxf(c[mt][nt][0], 0.f);
            out[i0 + 1] = fmaxf(c[mt][nt][1], 0.f);
            size_t i1 = i0 + (size_t)8 * N_DIM;
            out[i1]     = fmaxf(c[mt][nt][2], 0.f);
            out[i1 + 1] = fmaxf(c[mt][nt][3], 0.f);
        }
    }
}

// ---------------- launch -----------------------------------------------------
extern "C" void kernel_launch(void* const* d_in, const int* in_sizes, int n_in,
                              void* d_out, int out_size) {
    const float* x = nullptr;
    const float* cw = nullptr;
    const float* W = nullptr;
    const float* bias = nullptr;
    for (int i = 0; i < n_in; ++i) {
        switch (in_sizes[i]) {
            case M_DIM * I_DIM:         x    = (const float*)d_in[i]; break;
            case M_DIM * E_DIM:         cw   = (const float*)d_in[i]; break;
            case E_DIM * I_DIM * N_DIM: W    = (const float*)d_in[i]; break;
            case E_DIM * N_DIM:         bias = (const float*)d_in[i]; break;
            default: break;
        }
    }
    float* out = (float*)d_out;

    prep_w_kernel<<<2048, 256>>>(W);
    prep_a_kernel<<<8192, 256>>>(x, cw);
    prep_tail_kernel<<<(M_DIM * 64 + 64 * N_DIM + 255) / 256, 256>>>(cw, bias);

    cudaFuncSetAttribute(gemm_kernel, cudaFuncAttributeMaxDynamicSharedMemorySize,
                         STAGES * STAGE_BYTES);
    dim3 grid(N_DIM / BN, M_DIM / BM);  // (8, 32) = 256 CTAs
    gemm_kernel<<<grid, NTHREADS, STAGES * STAGE_BYTES>>>(out);
}

// round 8
// speedup vs baseline: 1.7830x; 1.0554x over previous
#include <cuda_runtime.h>
#include <cuda_fp16.h>
#include <cstdint>

// ---------------- problem dims ----------------
#define M_DIM 4096
#define N_DIM 1024
#define E_DIM 16
#define I_DIM 1024
#define K_DIM 16384
#define KS    16448          // K extended by one BK tile carrying cw/bias rank-16 term

// ---------------- GEMM config -----------------
#define BM 128
#define BN 128
#define BK 64
#define STAGES 3
#define NTHREADS 256

// smem: 3 stages of (A 16KB + B 16KB), then mbarriers
#define A_OFF 0
#define B_OFF 16384
#define STAGE_BYTES 32768
#define BAR_BASE (STAGES * STAGE_BYTES)          // 98304
#define FULL_OFF(s)  (BAR_BASE + (s) * 8)
#define EMPTY_OFF(s) (BAR_BASE + 24 + (s) * 8)
#define SMEM_TOTAL (BAR_BASE + 64)               // 98368 -> 2 CTAs/SM fits 227KB

// ---------------- device scratch --------------
__device__ __align__(1024) __half g_A[(size_t)M_DIM * KS];  // ~128.5 MiB: [cw*x | cw | 0]
__device__ __align__(1024) __half g_W[(size_t)KS * N_DIM];  // ~32.1 MiB:  [W ; bias ; 0]

// ---------------- fused prep ------------------
// range 0: W fp32->fp16 (float4 units)   range 1: A = cw*x (float4 units)
// range 2: tail K-tile (scalar)
__global__ void prep_all_kernel(const float* __restrict__ x,
                                const float* __restrict__ cw,
                                const float* __restrict__ W,
                                const float* __restrict__ bias) {
    const size_t NW4 = (size_t)K_DIM * N_DIM / 4;        // 4194304
    const size_t NA4 = (size_t)M_DIM * K_DIM / 4;        // 16777216
    const size_t NTL = (size_t)M_DIM * 64 + 64 * N_DIM;  // 327680
    const size_t total = NW4 + NA4 + NTL;
    size_t idx    = (size_t)blockIdx.x * blockDim.x + threadIdx.x;
    size_t stride = (size_t)gridDim.x * blockDim.x;
    for (; idx < total; idx += stride) {
        if (idx < NW4) {
            float4 w = *reinterpret_cast<const float4*>(W + idx * 4);
            *reinterpret_cast<__half2*>(g_W + idx * 4)     = __floats2half2_rn(w.x, w.y);
            *reinterpret_cast<__half2*>(g_W + idx * 4 + 2) = __floats2half2_rn(w.z, w.w);
        } else if (idx < NW4 + NA4) {
            size_t base = (idx - NW4) * 4;
            size_t b = base >> 14;
            int    k = (int)(base & 16383);
            float c = cw[b * E_DIM + (k >> 10)];
            float4 xv = *reinterpret_cast<const float4*>(x + (b << 10) + (k & 1023));
            size_t w = b * KS + k;
            *reinterpret_cast<__half2*>(g_A + w)     = __floats2half2_rn(c * xv.x, c * xv.y);
            *reinterpret_cast<__half2*>(g_A + w + 2) = __floats2half2_rn(c * xv.z, c * xv.w);
        } else {
            size_t j = idx - NW4 - NA4;
            if (j < (size_t)M_DIM * 64) {
                int b = (int)(j >> 6), e = (int)(j & 63);
                g_A[(size_t)b * KS + K_DIM + e] =
                    (e < E_DIM) ? __float2half_rn(cw[b * E_DIM + e]) : __half(0.f);
            } else {
                size_t t = j - (size_t)M_DIM * 64;
                int e = (int)(t >> 10), o = (int)(t & 1023);
                g_W[(size_t)(K_DIM + e) * N_DIM + o] =
                    (e < E_DIM) ? __float2half_rn(bias[e * N_DIM + o]) : __half(0.f);
            }
        }
    }
}

// ---------------- asm helpers ----------------
__device__ __forceinline__ void cp_async16(uint32_t s, const void* g) {
    asm volatile("cp.async.cg.shared.global [%0], [%1], 16;\n" :: "r"(s), "l"(g));
}
__device__ __forceinline__ void cpasync_arrive_noinc(uint32_t mbar) {
    asm volatile("cp.async.mbarrier.arrive.noinc.shared::cta.b64 [%0];" :: "r"(mbar) : "memory");
}
__device__ __forceinline__ void mbar_init(uint32_t a, uint32_t cnt) {
    asm volatile("mbarrier.init.shared.b64 [%0], %1;" :: "r"(a), "r"(cnt) : "memory");
}
__device__ __forceinline__ void mbar_arrive(uint32_t a) {
    asm volatile("mbarrier.arrive.shared.b64 _, [%0];" :: "r"(a) : "memory");
}
__device__ __forceinline__ void wait_parity(uint32_t mbar, uint32_t ph) {
    asm volatile("{\n\t.reg .pred P;\nWL%=:\n\t"
                 "mbarrier.try_wait.parity.acquire.cta.shared::cta.b64 P, [%0], %1, 0x989680;\n\t"
                 "@!P bra WL%=;\n\t}"
                 :: "r"(mbar), "r"(ph) : "memory");
}
__device__ __forceinline__ void ldsm_x4(uint32_t* r, uint32_t addr) {
    asm volatile("ldmatrix.sync.aligned.m8n8.x4.shared.b16 {%0,%1,%2,%3}, [%4];"
                 : "=r"(r[0]), "=r"(r[1]), "=r"(r[2]), "=r"(r[3]) : "r"(addr));
}
__device__ __forceinline__ void ldsm_x4_t(uint32_t* r, uint32_t addr) {
    asm volatile("ldmatrix.sync.aligned.m8n8.x4.trans.shared.b16 {%0,%1,%2,%3}, [%4];"
                 : "=r"(r[0]), "=r"(r[1]), "=r"(r[2]), "=r"(r[3]) : "r"(addr));
}
__device__ __forceinline__ void mma_f16(float* c, const uint32_t* a, const uint32_t* b) {
    asm volatile(
        "mma.sync.aligned.m16n8k16.row.col.f32.f16.f16.f32 "
        "{%0,%1,%2,%3}, {%4,%5,%6,%7}, {%8,%9}, {%0,%1,%2,%3};"
        : "+f"(c[0]), "+f"(c[1]), "+f"(c[2]), "+f"(c[3])
        : "r"(a[0]), "r"(a[1]), "r"(a[2]), "r"(a[3]), "r"(b[0]), "r"(b[1]));
}

// ---------------- tile loader (R7 layout) ----------------
__device__ __forceinline__ void issue_stage(uint32_t st,
                                            const __half* pA, const __half* pB,
                                            uint32_t dstA0, uint32_t dstB0) {
#pragma unroll
    for (int p = 0; p < 4; ++p)
        cp_async16(st + A_OFF + dstA0 + p * (32 * 128),
                   pA + (size_t)p * 32 * KS);
#pragma unroll
    for (int p = 0; p < 4; ++p)
        cp_async16(st + B_OFF + dstB0 + p * (16 * 256),
                   pB + (size_t)p * 16 * N_DIM);
}

// ---------------- main GEMM (R7 core, mbarrier ring) -------------------------
__global__ void __launch_bounds__(NTHREADS, 2)
gemm_kernel(float* __restrict__ out) {
    extern __shared__ char smem_raw[];
    const uint32_t smem_base = (uint32_t)__cvta_generic_to_shared(smem_raw);
    const int tid  = threadIdx.x;
    const int lane = tid & 31;
    const int warp = tid >> 5;
    const int wm   = warp >> 2;   // 0..1
    const int wn   = warp & 3;    // 0..3
    const int bm0  = blockIdx.y * BM;
    const int bn0  = blockIdx.x * BN;

    if (tid == 0) {
#pragma unroll
        for (int s = 0; s < STAGES; ++s) {
            mbar_init(smem_base + FULL_OFF(s),  NTHREADS);  // one noinc arrive / thread
            mbar_init(smem_base + EMPTY_OFF(s), 8);         // one arrive / warp
        }
    }
    __syncthreads();   // only block-wide barrier in the kernel

    const int arow = tid >> 3, ach = tid & 7;
    const int brow = tid >> 4, bch = tid & 15;
    const uint32_t dstA0 = (uint32_t)(arow * 128 + ((ach ^ (arow & 7)) << 4));
    const uint32_t dstB0 = (uint32_t)(brow * 256 + ((bch ^ (brow & 7)) << 4));
    const __half* pA = g_A + (size_t)(bm0 + arow) * KS + ach * 8;
    const __half* pB = g_W + (size_t)brow * N_DIM + bn0 + bch * 8;

    float c[4][4][4];
#pragma unroll
    for (int i = 0; i < 4; ++i)
#pragma unroll
        for (int j = 0; j < 4; ++j)
#pragma unroll
            for (int k = 0; k < 4; ++k) c[i][j][k] = 0.f;

    const int KT = KS / BK;  // 257

    // prologue: fill stages 0,1 (virgin -> no empty wait needed)
#pragma unroll
    for (int s = 0; s < STAGES - 1; ++s) {
        issue_stage(smem_base + s * STAGE_BYTES, pA, pB, dstA0, dstB0);
        cpasync_arrive_noinc(smem_base + FULL_OFF(s));
        pA += BK; pB += (size_t)BK * N_DIM;
    }

    const int a_row16 = lane & 15;
    const int hi_half = lane >> 4;

    int prod_s = STAGES - 1; uint32_t prod_ph = 1;
    int cons_s = 0;          uint32_t cons_ph = 0;

    for (int kt = 0; kt < KT; ++kt) {
        if (kt + STAGES - 1 < KT) {
            wait_parity(smem_base + EMPTY_OFF(prod_s), prod_ph);
            issue_stage(smem_base + prod_s * STAGE_BYTES, pA, pB, dstA0, dstB0);
            cpasync_arrive_noinc(smem_base + FULL_OFF(prod_s));
            pA += BK; pB += (size_t)BK * N_DIM;
            if (++prod_s == STAGES) { prod_s = 0; prod_ph ^= 1; }
        }

        wait_parity(smem_base + FULL_OFF(cons_s), cons_ph);
        const uint32_t st = smem_base + cons_s * STAGE_BYTES;
#pragma unroll
        for (int s = 0; s < 4; ++s) {       // four k16 steps per BK=64
            uint32_t a[4][4];
#pragma unroll
            for (int mt = 0; mt < 4; ++mt) {
                int row = wm * 64 + mt * 16 + a_row16;
                int ch  = s * 2 + hi_half;
                uint32_t off = (uint32_t)(row * 128 + ((ch ^ (row & 7)) << 4));
                ldsm_x4(a[mt], st + A_OFF + off);
            }
            uint32_t b[4][2];
#pragma unroll
            for (int nt2 = 0; nt2 < 2; ++nt2) {
                int r  = s * 16 + (lane & 15);
                int ch = wn * 4 + nt2 * 2 + hi_half;
                uint32_t off = (uint32_t)(r * 256 + ((ch ^ (r & 7)) << 4));
                uint32_t t[4];
                ldsm_x4_t(t, st + B_OFF + off);
                b[nt2 * 2][0] = t[0];     b[nt2 * 2][1] = t[1];
                b[nt2 * 2 + 1][0] = t[2]; b[nt2 * 2 + 1][1] = t[3];
            }
#pragma unroll
            for (int mt = 0; mt < 4; ++mt)
#pragma unroll
                for (int nt = 0; nt < 4; ++nt)
                    mma_f16(c[mt][nt], a[mt], b[nt]);
        }
        // release: final MMAs' register reads force the last LDSMs complete
        if (lane == 0) mbar_arrive(smem_base + EMPTY_OFF(cons_s));
        if (++cons_s == STAGES) { cons_s = 0; cons_ph ^= 1; }
    }

    // epilogue: ReLU + store (bias folded via K-extension)
    const int gr = lane >> 2;
    const int ct = lane & 3;
#pragma unroll
    for (int mt = 0; mt < 4; ++mt) {
#pragma unroll
        for (int nt = 0; nt < 4; ++nt) {
            int row = bm0 + wm * 64 + mt * 16 + gr;
            int o   = bn0 + wn * 32 + nt * 8 + ct * 2;
            size_t i0 = (size_t)row * N_DIM + o;
            out[i0]     = fmaxf(c[mt][nt][0], 0.f);
            out[i0 + 1] = fmaxf(c[mt][nt][1], 0.f);
            size_t i1 = i0 + (size_t)8 * N_DIM;
            out[i1]     = fmaxf(c[mt][nt][2], 0.f);
            out[i1 + 1] = fmaxf(c[mt][nt][3], 0.f);
        }
    }
}

// ---------------- launch -----------------------------------------------------
extern "C" void kernel_launch(void* const* d_in, const int* in_sizes, int n_in,
                              void* d_out, int out_size) {
    const float* x = nullptr;
    const float* cw = nullptr;
    const float* W = nullptr;
    const float* bias = nullptr;
    for (int i = 0; i < n_in; ++i) {
        switch (in_sizes[i]) {
            case M_DIM * I_DIM:         x    = (const float*)d_in[i]; break;
            case M_DIM * E_DIM:         cw   = (const float*)d_in[i]; break;
            case E_DIM * I_DIM * N_DIM: W    = (const float*)d_in[i]; break;
            case E_DIM * N_DIM:         bias = (const float*)d_in[i]; break;
            default: break;
        }
    }
    float* out = (float*)d_out;

    prep_all_kernel<<<8192, 256>>>(x, cw, W, bias);

    cudaFuncSetAttribute(gemm_kernel, cudaFuncAttributeMaxDynamicSharedMemorySize,
                         SMEM_TOTAL);
    dim3 grid(N_DIM / BN, M_DIM / BM);  // (8, 32) = 256 CTAs
    gemm_kernel<<<grid, NTHREADS, SMEM_TOTAL>>>(out);
}